// round 12
// baseline (speedup 1.0000x reference)
#include <cuda_runtime.h>
#include <cstdint>

// Problem: B=4, S=4096, H=16, Dk=Dv=64.  out = 0.95*M + sum_rows w*k v^T per head.
#define H_     16
#define DK_    64
#define DV_    64
#define HD_    1024           // floats per (b,s) row = H*64
#define DECAY_ 0.95f
#define NBLK_  296            // 148*2 -> exactly one wave at occupancy 2

// Raw fp32 staging (double buffered): K[k][m], V[k][n] stride 68, + w[64].
#define KSTR_    68
#define RAW_VF   4352         // float offset of V plane in raw buffer
#define RAW_WF   8704         // float offset of w
#define RAW_BUFF 8768         // floats per raw buffer
#define RAW_BYTES 35072       // bytes per raw buffer
// bf16x2 planes (single buffer, rebuilt each stage): word = pl[kp*72 + col].
#define PL_BASE  17536        // word offset after the two raw buffers
#define KHI_ (PL_BASE + 0)
#define KLO_ (PL_BASE + 2304)
#define VHI_ (PL_BASE + 4608)
#define VLO_ (PL_BASE + 6912)
#define SMEM_TOTAL ((PL_BASE + 9216) * 4)   // 107008 bytes

// hi = bf16x2{lo-half=bf16(x0), hi-half=bf16(x1)}; lo = bf16x2 of residuals
__device__ __forceinline__ void split2(float x0, float x1, uint32_t& hi, uint32_t& lo) {
    asm("cvt.rn.bf16x2.f32 %0, %1, %2;" : "=r"(hi) : "f"(x1), "f"(x0));
    float h0 = __uint_as_float(hi << 16);
    float h1 = __uint_as_float(hi & 0xffff0000u);
    float l0 = x0 - h0;
    float l1 = x1 - h1;
    asm("cvt.rn.bf16x2.f32 %0, %1, %2;" : "=r"(lo) : "f"(l1), "f"(l0));
}

__device__ __forceinline__ void mma16816(float* c, const uint32_t* a,
                                         uint32_t b0, uint32_t b1) {
    asm volatile(
        "mma.sync.aligned.m16n8k16.row.col.f32.bf16.bf16.f32 "
        "{%0,%1,%2,%3}, {%4,%5,%6,%7}, {%8,%9}, {%0,%1,%2,%3};"
        : "+f"(c[0]), "+f"(c[1]), "+f"(c[2]), "+f"(c[3])
        : "r"(a[0]), "r"(a[1]), "r"(a[2]), "r"(a[3]), "r"(b0), "r"(b1));
}

__device__ __forceinline__ void cp16(uint32_t dst, const float* src) {
    asm volatile("cp.async.cg.shared.global [%0], [%1], 16;" :: "r"(dst), "l"(src));
}

// Issue all cp.asyncs for one 64-row stage into raw buffer b; commit group.
#define ISSUE_STAGE(stg, b)                                                    \
    do {                                                                       \
        const int row0_ = (stg) * 64;                                          \
        const uint32_t bb_ = sbase + (uint32_t)(b) * RAW_BYTES;                \
        _Pragma("unroll")                                                      \
        for (int i = 0; i < 4; ++i) {                                          \
            const int idx = i * 256 + tid;                                     \
            const int row = idx >> 4;                                          \
            const int seg = idx & 15;                                          \
            const uint32_t d = (uint32_t)(row * 272 + seg * 16);               \
            const size_t g = (size_t)(row0_ + row) * HD_ + seg * 4;            \
            cp16(bb_ + d, kbase + g);                                          \
            cp16(bb_ + 17408u + d, vbase + g);                                 \
        }                                                                      \
        if (tid < 16) cp16(bb_ + 34816u + tid * 16, ws + row0_ + tid * 4);     \
        asm volatile("cp.async.commit_group;" ::: "memory");                   \
    } while (0)

__global__ __launch_bounds__(256, 2)
void l1w_main_kernel(const float* __restrict__ keys,
                     const float* __restrict__ values,
                     const float* __restrict__ ws,
                     float* __restrict__ out) {
    extern __shared__ __align__(16) float dsm[];
    uint32_t* pl = (uint32_t*)dsm;
    uint32_t sbase;
    asm("{ .reg .u64 t; cvta.to.shared.u64 t, %1; cvt.u32.u64 %0, t; }"
        : "=r"(sbase) : "l"(dsm));

    const int tid  = threadIdx.x;
    const int wid  = tid >> 5;
    const int lane = tid & 31;
    const int bid  = blockIdx.x;

    // bid -> (head h, first stage s0, stage count nt); 256 stages of 64 rows/head.
    int h, nt, s0;
    if (bid < 152) {                        // heads 0..7: 19 blocks each
        h = bid / 19;
        const int ci = bid - 19 * h;
        if (ci < 9) { nt = 14; s0 = 14 * ci; }
        else        { nt = 13; s0 = 126 + 13 * (ci - 9); }
    } else {                                // heads 8..15: 18 blocks each
        const int r = bid - 152;
        h = 8 + r / 18;
        const int ci = r - 18 * (h - 8);
        if (ci < 4) { nt = 15; s0 = 15 * ci; }
        else        { nt = 14; s0 = 60 + 14 * (ci - 4); }
    }

    const float* kbase = keys   + (size_t)h * DK_;
    const float* vbase = values + (size_t)h * DV_;

    // MMA warp tiling: 4m x 2n. Warp covers rows 16*wm..+15, cols 32*wn..+31.
    const int wm = wid & 3;
    const int wn = wid >> 2;
    const int r2 = lane >> 2;
    const int c2 = lane & 3;

    // Convert mapping: thread owns k-pair kp (rows 2kp,2kp+1), cols 8*segc..+7.
    const int kp   = tid >> 3;
    const int segc = tid & 7;

    float cacc[4][4];
#pragma unroll
    for (int n2 = 0; n2 < 4; ++n2)
#pragma unroll
        for (int i = 0; i < 4; ++i) cacc[n2][i] = 0.0f;

    ISSUE_STAGE(s0, 0);

    for (int s = 0; s < nt; ++s) {
        if (s + 1 < nt) {
            ISSUE_STAGE(s0 + s + 1, (s + 1) & 1);
            asm volatile("cp.async.wait_group 1;" ::: "memory");
        } else {
            asm volatile("cp.async.wait_group 0;" ::: "memory");
        }
        __syncthreads();                     // raw stage s visible

        // ---- convert once: raw fp32 -> bf16 hi/lo planes (w folded into V) ----
        {
            const float* Kr = dsm + (s & 1) * RAW_BUFF;
            const float* Vr = Kr + RAW_VF;
            const float* Wr = Kr + RAW_WF;
            const int rb = 2 * kp * KSTR_ + 8 * segc;
            float4 k0a = *(const float4*)(Kr + rb);
            float4 k0b = *(const float4*)(Kr + rb + 4);
            float4 k1a = *(const float4*)(Kr + rb + KSTR_);
            float4 k1b = *(const float4*)(Kr + rb + KSTR_ + 4);
            float4 v0a = *(const float4*)(Vr + rb);
            float4 v0b = *(const float4*)(Vr + rb + 4);
            float4 v1a = *(const float4*)(Vr + rb + KSTR_);
            float4 v1b = *(const float4*)(Vr + rb + KSTR_ + 4);
            float2 w2  = *(const float2*)(Wr + 2 * kp);

            uint32_t kh[8], kl[8], vh[8], vl[8];
            const float* k0 = &k0a.x;  // k0a,k0b contiguous in regs? use arrays
            float K0[8] = {k0a.x,k0a.y,k0a.z,k0a.w,k0b.x,k0b.y,k0b.z,k0b.w};
            float K1[8] = {k1a.x,k1a.y,k1a.z,k1a.w,k1b.x,k1b.y,k1b.z,k1b.w};
            float V0[8] = {v0a.x,v0a.y,v0a.z,v0a.w,v0b.x,v0b.y,v0b.z,v0b.w};
            float V1[8] = {v1a.x,v1a.y,v1a.z,v1a.w,v1b.x,v1b.y,v1b.z,v1b.w};
            (void)k0;
#pragma unroll
            for (int j = 0; j < 8; ++j) {
                split2(K0[j], K1[j], kh[j], kl[j]);
                split2(V0[j] * w2.x, V1[j] * w2.y, vh[j], vl[j]);
            }
            const uint32_t wb = (uint32_t)(kp * 72 + 8 * segc);
            *(uint4*)(pl + KHI_ + wb)     = make_uint4(kh[0],kh[1],kh[2],kh[3]);
            *(uint4*)(pl + KHI_ + wb + 4) = make_uint4(kh[4],kh[5],kh[6],kh[7]);
            *(uint4*)(pl + KLO_ + wb)     = make_uint4(kl[0],kl[1],kl[2],kl[3]);
            *(uint4*)(pl + KLO_ + wb + 4) = make_uint4(kl[4],kl[5],kl[6],kl[7]);
            *(uint4*)(pl + VHI_ + wb)     = make_uint4(vh[0],vh[1],vh[2],vh[3]);
            *(uint4*)(pl + VHI_ + wb + 4) = make_uint4(vh[4],vh[5],vh[6],vh[7]);
            *(uint4*)(pl + VLO_ + wb)     = make_uint4(vl[0],vl[1],vl[2],vl[3]);
            *(uint4*)(pl + VLO_ + wb + 4) = make_uint4(vl[4],vl[5],vl[6],vl[7]);
        }
        __syncthreads();                     // planes ready

        // ---- MMA phase: 4 k-steps, warp tile 16m x 32n, 3 products ----
#pragma unroll
        for (int st = 0; st < 4; ++st) {
            const uint32_t kro = (uint32_t)((8 * st + c2) * 72);
            const uint32_t cc  = (uint32_t)(16 * wm + r2);
            uint32_t aH[4], aL[4];
            aH[0] = pl[KHI_ + kro + cc];
            aH[1] = pl[KHI_ + kro + cc + 8];
            aH[2] = pl[KHI_ + kro + 288 + cc];
            aH[3] = pl[KHI_ + kro + 288 + cc + 8];
            aL[0] = pl[KLO_ + kro + cc];
            aL[1] = pl[KLO_ + kro + cc + 8];
            aL[2] = pl[KLO_ + kro + 288 + cc];
            aL[3] = pl[KLO_ + kro + 288 + cc + 8];
#pragma unroll
            for (int n2 = 0; n2 < 4; ++n2) {
                const uint32_t nn = (uint32_t)(32 * wn + 8 * n2 + r2);
                const uint32_t bH0 = pl[VHI_ + kro + nn];
                const uint32_t bH1 = pl[VHI_ + kro + 288 + nn];
                const uint32_t bL0 = pl[VLO_ + kro + nn];
                const uint32_t bL1 = pl[VLO_ + kro + 288 + nn];
                mma16816(cacc[n2], aH, bH0, bH1);
                mma16816(cacc[n2], aH, bL0, bL1);
                mma16816(cacc[n2], aL, bH0, bH1);
            }
        }
        __syncthreads();                     // planes free for next convert
    }

    // ---- epilogue: RED.ADD 16x32 warp tile into pre-decayed out ----
    float* outp = out + ((size_t)h << 12);
#pragma unroll
    for (int n2 = 0; n2 < 4; ++n2) {
        const int row = 16 * wm + r2;
        const int col = 32 * wn + 8 * n2 + 2 * c2;
        atomicAdd(outp + (size_t)row * DV_ + col,           cacc[n2][0]);
        atomicAdd(outp + (size_t)row * DV_ + col + 1,       cacc[n2][1]);
        atomicAdd(outp + (size_t)(row + 8) * DV_ + col,     cacc[n2][2]);
        atomicAdd(outp + (size_t)(row + 8) * DV_ + col + 1, cacc[n2][3]);
    }
}

__global__ void l1w_init_kernel(const float* __restrict__ memory,
                                float* __restrict__ out) {
    const int e4 = blockIdx.x * blockDim.x + threadIdx.x;  // 0..16383 float4
    float4 m = ((const float4*)memory)[e4];
    m.x *= DECAY_; m.y *= DECAY_; m.z *= DECAY_; m.w *= DECAY_;
    ((float4*)out)[e4] = m;
}

extern "C" void kernel_launch(void* const* d_in, const int* in_sizes, int n_in,
                              void* d_out, int out_size) {
    const float* memory = (const float*)d_in[0];   // (16,64,64)
    const float* keys   = (const float*)d_in[1];   // (4,4096,16,64)
    const float* values = (const float*)d_in[2];   // (4,4096,16,64)
    const float* ws     = (const float*)d_in[3];   // (4,4096)
    float* out = (float*)d_out;                    // (16,64,64)

    cudaFuncSetAttribute(l1w_main_kernel,
                         cudaFuncAttributeMaxDynamicSharedMemorySize,
                         SMEM_TOTAL);

    l1w_init_kernel<<<128, 128>>>(memory, out);
    l1w_main_kernel<<<NBLK_, 256, SMEM_TOTAL>>>(keys, values, ws, out);
}

// round 14
// speedup vs baseline: 1.1903x; 1.1903x over previous
#include <cuda_runtime.h>
#include <cstdint>

// Problem: B=4, S=4096, H=16, Dk=Dv=64.  out = 0.95*M + sum_rows w*k v^T per head.
#define H_     16
#define DK_    64
#define DV_    64
#define HD_    1024           // floats per (b,s) row = H*64
#define DECAY_ 0.95f
#define NBLK_  296            // 148*2 -> exactly one wave at occupancy 2

// bf16x2 planes, double buffered. Word addr: buf*BUFW + PLANE + kp*72 + col.
// kp = k-row-pair (0..31), col = m or n (0..63). Stride 72 => fragment LDS
// banks (8*c2 + r2) % 32 -> conflict-free.
#define KHI_  0
#define KLO_  2304
#define VHI_  4608
#define VLO_  6912
#define BUFW_ 9216
#define SMEM_BYTES (2 * BUFW_ * 4)   // 73728

// hi = bf16x2{lo-half=bf16(x0), hi-half=bf16(x1)}; lo = bf16x2 of residuals
__device__ __forceinline__ void split2(float x0, float x1, uint32_t& hi, uint32_t& lo) {
    asm("cvt.rn.bf16x2.f32 %0, %1, %2;" : "=r"(hi) : "f"(x1), "f"(x0));
    float h0 = __uint_as_float(hi << 16);
    float h1 = __uint_as_float(hi & 0xffff0000u);
    float l0 = x0 - h0;
    float l1 = x1 - h1;
    asm("cvt.rn.bf16x2.f32 %0, %1, %2;" : "=r"(lo) : "f"(l1), "f"(l0));
}

__device__ __forceinline__ void mma16816(float* c, const uint32_t* a,
                                         uint32_t b0, uint32_t b1) {
    asm volatile(
        "mma.sync.aligned.m16n8k16.row.col.f32.bf16.bf16.f32 "
        "{%0,%1,%2,%3}, {%4,%5,%6,%7}, {%8,%9}, {%0,%1,%2,%3};"
        : "+f"(c[0]), "+f"(c[1]), "+f"(c[2]), "+f"(c[3])
        : "r"(a[0]), "r"(a[1]), "r"(a[2]), "r"(a[3]), "r"(b0), "r"(b1));
}

// ---- load one stage into registers (8 LDG.128 + 1 LDG.64 per thread) ----
#define LOAD_STAGE(stg)                                                        \
    do {                                                                       \
        const int r0_ = (stg) * 64 + 2 * kp;                                   \
        const float* kp_ = kbase + (size_t)r0_ * HD_ + 8 * segc;               \
        const float* vp_ = vbase + (size_t)r0_ * HD_ + 8 * segc;               \
        sk[0] = *(const float4*)(kp_);                                         \
        sk[1] = *(const float4*)(kp_ + 4);                                     \
        sk[2] = *(const float4*)(kp_ + HD_);                                   \
        sk[3] = *(const float4*)(kp_ + HD_ + 4);                               \
        sv[0] = *(const float4*)(vp_);                                         \
        sv[1] = *(const float4*)(vp_ + 4);                                     \
        sv[2] = *(const float4*)(vp_ + HD_);                                   \
        sv[3] = *(const float4*)(vp_ + HD_ + 4);                               \
        w2 = *(const float2*)(ws + r0_);                                       \
    } while (0)

// ---- split in registers, store bf16x2 planes into buffer b ----
#define STORE_STAGE(b)                                                         \
    do {                                                                       \
        uint32_t* pb_ = pl + (b) * BUFW_;                                      \
        const uint32_t wb_ = (uint32_t)(kp * 72 + 8 * segc);                   \
        float K0[8] = {sk[0].x, sk[0].y, sk[0].z, sk[0].w,                     \
                       sk[1].x, sk[1].y, sk[1].z, sk[1].w};                    \
        float K1[8] = {sk[2].x, sk[2].y, sk[2].z, sk[2].w,                     \
                       sk[3].x, sk[3].y, sk[3].z, sk[3].w};                    \
        float V0[8] = {sv[0].x, sv[0].y, sv[0].z, sv[0].w,                     \
                       sv[1].x, sv[1].y, sv[1].z, sv[1].w};                    \
        float V1[8] = {sv[2].x, sv[2].y, sv[2].z, sv[2].w,                     \
                       sv[3].x, sv[3].y, sv[3].z, sv[3].w};                    \
        uint32_t kh[8], kl[8], vh[8], vl[8];                                   \
        _Pragma("unroll")                                                      \
        for (int j = 0; j < 8; ++j) {                                          \
            split2(K0[j], K1[j], kh[j], kl[j]);                                \
            split2(V0[j] * w2.x, V1[j] * w2.y, vh[j], vl[j]);                  \
        }                                                                      \
        *(uint4*)(pb_ + KHI_ + wb_)     = make_uint4(kh[0], kh[1], kh[2], kh[3]); \
        *(uint4*)(pb_ + KHI_ + wb_ + 4) = make_uint4(kh[4], kh[5], kh[6], kh[7]); \
        *(uint4*)(pb_ + KLO_ + wb_)     = make_uint4(kl[0], kl[1], kl[2], kl[3]); \
        *(uint4*)(pb_ + KLO_ + wb_ + 4) = make_uint4(kl[4], kl[5], kl[6], kl[7]); \
        *(uint4*)(pb_ + VHI_ + wb_)     = make_uint4(vh[0], vh[1], vh[2], vh[3]); \
        *(uint4*)(pb_ + VHI_ + wb_ + 4) = make_uint4(vh[4], vh[5], vh[6], vh[7]); \
        *(uint4*)(pb_ + VLO_ + wb_)     = make_uint4(vl[0], vl[1], vl[2], vl[3]); \
        *(uint4*)(pb_ + VLO_ + wb_ + 4) = make_uint4(vl[4], vl[5], vl[6], vl[7]); \
    } while (0)

__global__ __launch_bounds__(256, 2)
void l1w_main_kernel(const float* __restrict__ keys,
                     const float* __restrict__ values,
                     const float* __restrict__ ws,
                     float* __restrict__ out) {
    extern __shared__ __align__(16) uint32_t pl[];

    const int tid  = threadIdx.x;
    const int wid  = tid >> 5;
    const int lane = tid & 31;
    const int bid  = blockIdx.x;

    // bid -> (head h, first stage s0, stage count nt); 256 stages of 64 rows/head.
    int h, nt, s0;
    if (bid < 152) {                        // heads 0..7: 19 blocks each
        h = bid / 19;
        const int ci = bid - 19 * h;
        if (ci < 9) { nt = 14; s0 = 14 * ci; }
        else        { nt = 13; s0 = 126 + 13 * (ci - 9); }
    } else {                                // heads 8..15: 18 blocks each
        const int r = bid - 152;
        h = 8 + r / 18;
        const int ci = r - 18 * (h - 8);
        if (ci < 4) { nt = 15; s0 = 15 * ci; }
        else        { nt = 14; s0 = 60 + 14 * (ci - 4); }
    }

    const float* kbase = keys   + (size_t)h * DK_;
    const float* vbase = values + (size_t)h * DV_;

    // fill mapping: thread owns k-pair kp (rows 2kp,2kp+1), cols 8*segc..+7
    const int kp   = tid >> 3;
    const int segc = tid & 7;
    // MMA mapping: 8 warps tile 2m x 4n -> warp covers 32 rows x 16 cols
    const int wm = wid & 1;
    const int wn = wid >> 1;
    const int r2 = lane >> 2;
    const int c2 = lane & 3;

    float cacc[2][2][4];
#pragma unroll
    for (int mt = 0; mt < 2; ++mt)
#pragma unroll
        for (int n2 = 0; n2 < 2; ++n2)
#pragma unroll
            for (int i = 0; i < 4; ++i) cacc[mt][n2][i] = 0.0f;

    float4 sk[4], sv[4];
    float2 w2;

    LOAD_STAGE(s0);
    STORE_STAGE(0);
    __syncthreads();

    for (int s = 0; s < nt; ++s) {
        if (s + 1 < nt) LOAD_STAGE(s0 + s + 1);   // LDGs in flight under MMAs

        // ---- MMA phase from buffer s&1 ----
        {
            const uint32_t* sm = pl + (s & 1) * BUFW_;
#pragma unroll
            for (int st = 0; st < 4; ++st) {
                const uint32_t kro = (uint32_t)((8 * st + c2) * 72);
                uint32_t aH[2][4], aL[2][4];
#pragma unroll
                for (int mt = 0; mt < 2; ++mt) {
                    const uint32_t cc = (uint32_t)(32 * wm + 16 * mt + r2);
                    aH[mt][0] = sm[KHI_ + kro + cc];
                    aH[mt][1] = sm[KHI_ + kro + cc + 8];
                    aH[mt][2] = sm[KHI_ + kro + 288 + cc];
                    aH[mt][3] = sm[KHI_ + kro + 288 + cc + 8];
                    aL[mt][0] = sm[KLO_ + kro + cc];
                    aL[mt][1] = sm[KLO_ + kro + cc + 8];
                    aL[mt][2] = sm[KLO_ + kro + 288 + cc];
                    aL[mt][3] = sm[KLO_ + kro + 288 + cc + 8];
                }
#pragma unroll
                for (int n2 = 0; n2 < 2; ++n2) {
                    const uint32_t nn = (uint32_t)(16 * wn + 8 * n2 + r2);
                    const uint32_t bH0 = sm[VHI_ + kro + nn];
                    const uint32_t bH1 = sm[VHI_ + kro + 288 + nn];
                    const uint32_t bL0 = sm[VLO_ + kro + nn];
                    const uint32_t bL1 = sm[VLO_ + kro + 288 + nn];
#pragma unroll
                    for (int mt = 0; mt < 2; ++mt) {
                        mma16816(cacc[mt][n2], aH[mt], bH0, bH1);
                        mma16816(cacc[mt][n2], aH[mt], bL0, bL1);
                        mma16816(cacc[mt][n2], aL[mt], bH0, bH1);
                    }
                }
            }
        }

        if (s + 1 < nt) STORE_STAGE((s + 1) & 1);
        __syncthreads();
    }

    // ---- epilogue: RED.ADD 32x16 warp tile into pre-decayed out ----
    float* outp = out + ((size_t)h << 12);
#pragma unroll
    for (int mt = 0; mt < 2; ++mt)
#pragma unroll
        for (int n2 = 0; n2 < 2; ++n2) {
            const int row = 32 * wm + 16 * mt + r2;
            const int col = 16 * wn + 8 * n2 + 2 * c2;
            atomicAdd(outp + (size_t)row * DV_ + col,           cacc[mt][n2][0]);
            atomicAdd(outp + (size_t)row * DV_ + col + 1,       cacc[mt][n2][1]);
            atomicAdd(outp + (size_t)(row + 8) * DV_ + col,     cacc[mt][n2][2]);
            atomicAdd(outp + (size_t)(row + 8) * DV_ + col + 1, cacc[mt][n2][3]);
        }
}

__global__ void l1w_init_kernel(const float* __restrict__ memory,
                                float* __restrict__ out) {
    const int e4 = blockIdx.x * blockDim.x + threadIdx.x;  // 0..16383 float4
    float4 m = ((const float4*)memory)[e4];
    m.x *= DECAY_; m.y *= DECAY_; m.z *= DECAY_; m.w *= DECAY_;
    ((float4*)out)[e4] = m;
}

extern "C" void kernel_launch(void* const* d_in, const int* in_sizes, int n_in,
                              void* d_out, int out_size) {
    const float* memory = (const float*)d_in[0];   // (16,64,64)
    const float* keys   = (const float*)d_in[1];   // (4,4096,16,64)
    const float* values = (const float*)d_in[2];   // (4,4096,16,64)
    const float* ws     = (const float*)d_in[3];   // (4,4096)
    float* out = (float*)d_out;                    // (16,64,64)

    cudaFuncSetAttribute(l1w_main_kernel,
                         cudaFuncAttributeMaxDynamicSharedMemorySize,
                         SMEM_BYTES);

    l1w_init_kernel<<<128, 128>>>(memory, out);
    l1w_main_kernel<<<NBLK_, 256, SMEM_BYTES>>>(keys, values, ws, out);
}